// round 1
// baseline (speedup 1.0000x reference)
#include <cuda_runtime.h>
#include <math.h>

#define N_ROWS 8192
#define DIM    128

// Packed per-(i,o) weights, computed by prep_kernel each call (cheap, deterministic).
// w.x = g (clipped), w.y = ln2*Wr, w.z = ln2*Wi, w.w = -pi*g*Wi ;  Q = +pi*g*Wr
__device__ float4 g_Wpack[DIM * DIM];
__device__ float  g_Qarr [DIM * DIM];

__global__ void NPU_prep_kernel(const float* __restrict__ Wr,
                                const float* __restrict__ Wi,
                                const float* __restrict__ G) {
    int idx = blockIdx.x * blockDim.x + threadIdx.x;
    if (idx >= DIM * DIM) return;
    float g = G[idx];
    g = fminf(fmaxf(g, 0.0f), 1.0f);
    float wr = Wr[idx];
    float wi = Wi[idx];
    const float LN2 = 0.69314718055994530942f;
    const float PI  = 3.14159265358979323846f;
    float4 w;
    w.x = g;
    w.y = LN2 * wr;      // multiplies lg2(R) into A
    w.z = LN2 * wi;      // multiplies lg2(R) into B
    w.w = -PI * g * wi;  // sign (x<0) contribution to A
    g_Wpack[idx] = w;
    g_Qarr[idx]  = PI * g * wr;  // sign contribution to B
}

#define NT 64            // rows per block
#define NTP 65           // padded row-smem stride (kills 32-way STS conflict)
#define OT 64            // cols per block
#define NR 4             // rows per thread
#define OR 4             // cols per thread
#define THREADS 256      // (OT/OR) x (NT/NR) = 16 x 16

// smem: weights float4 [DIM][OT] + Q float [DIM][OT] + rows float2 [DIM][NTP]
#define SMEM_W4_BYTES (DIM * OT * 16)
#define SMEM_Q_BYTES  (DIM * OT * 4)
#define SMEM_R_BYTES  (DIM * NTP * 8)
#define SMEM_TOTAL    (SMEM_W4_BYTES + SMEM_Q_BYTES + SMEM_R_BYTES)

__global__ __launch_bounds__(THREADS, 1)
void NPU_main_kernel(const float* __restrict__ x, float* __restrict__ out) {
    extern __shared__ char smem[];
    float4* sW4  = (float4*)smem;                                   // [DIM][OT]
    float*  sQ   = (float*)(smem + SMEM_W4_BYTES);                  // [DIM][OT]
    float2* sRow = (float2*)(smem + SMEM_W4_BYTES + SMEM_Q_BYTES);  // [DIM][NTP]

    const int tid = threadIdx.x;
    const int n0  = blockIdx.x * NT;
    const int o0  = blockIdx.y * OT;

    // ---- Stage weights for this o-tile: all i, OT cols ----
    for (int k = tid; k < DIM * OT; k += THREADS) {
        int i  = k >> 6;      // /OT
        int ol = k & (OT - 1);
        sW4[k] = g_Wpack[i * DIM + o0 + ol];
        sQ[k]  = g_Qarr [i * DIM + o0 + ol];
    }
    // ---- Stage rows: am1 = |x|+eps-1, negf = (x<0) ----
    for (int k = tid; k < NT * DIM; k += THREADS) {
        int nl = k >> 7;      // /DIM
        int i  = k & (DIM - 1);
        float xv = x[(n0 + nl) * DIM + i];           // coalesced
        float a  = fabsf(xv) + 1e-36f;
        sRow[i * NTP + nl] = make_float2(a - 1.0f, xv < 0.0f ? 1.0f : 0.0f);
    }
    __syncthreads();

    const int to = (tid & 15) * OR;   // col offset within tile
    const int tn = (tid >> 4) * NR;   // row offset within tile

    float A[NR][OR], B[NR][OR];
    #pragma unroll
    for (int r = 0; r < NR; r++)
        #pragma unroll
        for (int j = 0; j < OR; j++) { A[r][j] = 0.0f; B[r][j] = 0.0f; }

    #pragma unroll 1
    for (int i = 0; i < DIM; i++) {
        float4 w[OR];
        float  q[OR];
        #pragma unroll
        for (int j = 0; j < OR; j++) {
            w[j] = sW4[i * OT + to + j];
            q[j] = sQ [i * OT + to + j];
        }
        float2 rv[NR];
        #pragma unroll
        for (int r = 0; r < NR; r++) rv[r] = sRow[i * NTP + tn + r];

        #pragma unroll
        for (int r = 0; r < NR; r++) {
            #pragma unroll
            for (int j = 0; j < OR; j++) {
                float R = fmaf(rv[r].x, w[j].x, 1.0f);   // a*g + (1-g), single rounding
                float t = __log2f(R);                    // MUFU.LG2
                A[r][j] = fmaf(rv[r].y, w[j].w, A[r][j]);  // -pi*g*Wi if x<0
                A[r][j] = fmaf(t,       w[j].y, A[r][j]);  // + lg2R * ln2*Wr
                B[r][j] = fmaf(rv[r].y, q[j],   B[r][j]);  // +pi*g*Wr if x<0
                B[r][j] = fmaf(t,       w[j].z, B[r][j]);  // + lg2R * ln2*Wi
            }
        }
    }

    // ---- Epilogue: out = exp(A) * cos(B), accurate libm (only 16 elems/thread) ----
    #pragma unroll
    for (int r = 0; r < NR; r++) {
        float4 v;
        v.x = expf(A[r][0]) * cosf(B[r][0]);
        v.y = expf(A[r][1]) * cosf(B[r][1]);
        v.z = expf(A[r][2]) * cosf(B[r][2]);
        v.w = expf(A[r][3]) * cosf(B[r][3]);
        *(float4*)&out[(n0 + tn + r) * DIM + o0 + to] = v;
    }
}

extern "C" void kernel_launch(void* const* d_in, const int* in_sizes, int n_in,
                              void* d_out, int out_size) {
    const float* x  = (const float*)d_in[0];
    const float* Wr = (const float*)d_in[1];
    const float* Wi = (const float*)d_in[2];
    const float* G  = (const float*)d_in[3];
    float* out = (float*)d_out;
    (void)in_sizes; (void)n_in; (void)out_size;

    NPU_prep_kernel<<<(DIM * DIM + 255) / 256, 256>>>(Wr, Wi, G);

    cudaFuncSetAttribute(NPU_main_kernel,
                         cudaFuncAttributeMaxDynamicSharedMemorySize, SMEM_TOTAL);
    dim3 grid(N_ROWS / NT, DIM / OT);
    NPU_main_kernel<<<grid, THREADS, SMEM_TOTAL>>>(x, out);
}

// round 3
// speedup vs baseline: 1.7901x; 1.7901x over previous
#include <cuda_runtime.h>
#include <math.h>

#define N_ROWS 8192
#define DIM    128

#define NT 128           // rows per block
#define OT 64            // cols per block
#define KC 32            // i-chunk staged in smem
#define NCH (DIM / KC)   // 4 chunks
#define THREADS 512
#define NR 4             // rows per thread
#define OR 4             // cols per thread
#define NTP 129          // padded float2 row stride (conflict-free staging)

// ---- packed weights (prep kernel output) ----
// gG   : g (clipped)
// gWyz : (ln2*Wr, ln2*Wi)   -> multiplies lg2(R) into (A,B) with one FFMA2
// gPQ  : (-pi*g*Wi, pi*g*Wr)-> sign (x<0) contribution to (A,B), one FFMA2
__device__ float  gG  [DIM * DIM];
__device__ float2 gWyz[DIM * DIM];
__device__ float2 gPQ [DIM * DIM];

__global__ void NPU_prep_kernel(const float* __restrict__ Wr,
                                const float* __restrict__ Wi,
                                const float* __restrict__ G) {
    int idx = blockIdx.x * blockDim.x + threadIdx.x;
    if (idx >= DIM * DIM) return;
    float g = fminf(fmaxf(G[idx], 0.0f), 1.0f);
    float wr = Wr[idx];
    float wi = Wi[idx];
    const float LN2 = 0.69314718055994530942f;
    const float PI  = 3.14159265358979323846f;
    gG[idx]   = g;
    gWyz[idx] = make_float2(LN2 * wr, LN2 * wi);
    gPQ[idx]  = make_float2(-PI * g * wi, PI * g * wr);
}

// ---- smem layout (single buffer, 74KB) ----
#define SM_G_BYTES   (KC * OT * 4)     //  8192
#define SM_WYZ_BYTES (KC * OT * 8)     // 16384
#define SM_PQ_BYTES  (KC * OT * 8)     // 16384
#define SM_ROW_BYTES (KC * NTP * 8)    // 33024
#define SM_WYZ_OFF   (SM_G_BYTES)
#define SM_PQ_OFF    (SM_WYZ_OFF + SM_WYZ_BYTES)
#define SM_ROW_OFF   (SM_PQ_OFF + SM_PQ_BYTES)
#define SMEM_TOTAL   (SM_ROW_OFF + SM_ROW_BYTES)

#define FMA_F32X2(d, a, b) \
    asm("fma.rn.f32x2 %0, %1, %2, %0;" : "+l"(d) : "l"(a), "l"(b))

#define PACK_DUP(d, s) \
    asm("mov.b64 %0, {%1, %1};" : "=l"(d) : "r"(s))

__global__ __launch_bounds__(THREADS, 1)
void NPU_main_kernel(const float* __restrict__ x, float* __restrict__ out) {
    extern __shared__ char smem[];
    float*  sG   = (float*) smem;                          // [KC][OT]
    float2* sWyz = (float2*)(smem + SM_WYZ_OFF);           // [KC][OT]
    float2* sPQ  = (float2*)(smem + SM_PQ_OFF);            // [KC][OT]
    float2* sRow = (float2*)(smem + SM_ROW_OFF);           // [KC][NTP] (am1, negf)

    const int tid = threadIdx.x;
    const int n0  = blockIdx.x * NT;
    const int o0  = blockIdx.y * OT;
    const int to  = (tid & 15) * OR;   // col offset in tile
    const int tn  = (tid >> 4) * NR;   // row offset in tile

    unsigned long long AB[NR][OR];
    #pragma unroll
    for (int r = 0; r < NR; r++)
        #pragma unroll
        for (int j = 0; j < OR; j++) AB[r][j] = 0ULL;

    for (int c = 0; c < NCH; c++) {
        const int i0 = c * KC;
        __syncthreads();   // previous chunk fully consumed

        // ---- stage weights: g as float4, wyz/pq as float4 (2x float2) ----
        {
            int ir = tid >> 4;            // 0..31
            int o4 = (tid & 15) * 4;
            *(float4*)&sG[ir * OT + o4] =
                *(const float4*)&gG[(i0 + ir) * DIM + o0 + o4];
        }
        #pragma unroll
        for (int k = tid; k < KC * OT / 2; k += THREADS) {
            int ir = k >> 5;              // 0..31
            int o2 = (k & 31) * 2;
            *(float4*)&sWyz[ir * OT + o2] =
                *(const float4*)&gWyz[(i0 + ir) * DIM + o0 + o2];
            *(float4*)&sPQ[ir * OT + o2] =
                *(const float4*)&gPQ[(i0 + ir) * DIM + o0 + o2];
        }
        // ---- stage rows: am1 = |x|+eps-1, negf = (x<0) ; [i][n] layout ----
        #pragma unroll
        for (int k = tid; k < NT * KC / 4; k += THREADS) {
            int n  = k >> 3;              // 0..127
            int i4 = (k & 7) * 4;
            float4 xv = *(const float4*)&x[(n0 + n) * DIM + i0 + i4];
            sRow[(i4 + 0) * NTP + n] =
                make_float2((fabsf(xv.x) + 1e-36f) - 1.0f, xv.x < 0.0f ? 1.0f : 0.0f);
            sRow[(i4 + 1) * NTP + n] =
                make_float2((fabsf(xv.y) + 1e-36f) - 1.0f, xv.y < 0.0f ? 1.0f : 0.0f);
            sRow[(i4 + 2) * NTP + n] =
                make_float2((fabsf(xv.z) + 1e-36f) - 1.0f, xv.z < 0.0f ? 1.0f : 0.0f);
            sRow[(i4 + 3) * NTP + n] =
                make_float2((fabsf(xv.w) + 1e-36f) - 1.0f, xv.w < 0.0f ? 1.0f : 0.0f);
        }
        __syncthreads();

        // ---- hot loop ----
        #pragma unroll 2
        for (int i = 0; i < KC; i++) {
            float4 gv = *(const float4*)&sG[i * OT + to];
            ulonglong2 w01 = *(const ulonglong2*)&sWyz[i * OT + to];
            ulonglong2 w23 = *(const ulonglong2*)&sWyz[i * OT + to + 2];
            ulonglong2 p01 = *(const ulonglong2*)&sPQ [i * OT + to];
            ulonglong2 p23 = *(const ulonglong2*)&sPQ [i * OT + to + 2];
            unsigned long long wj[OR] = {w01.x, w01.y, w23.x, w23.y};
            unsigned long long pj[OR] = {p01.x, p01.y, p23.x, p23.y};
            float gj[OR] = {gv.x, gv.y, gv.z, gv.w};

            float2 rv[NR];
            unsigned long long nfnf[NR];
            #pragma unroll
            for (int r = 0; r < NR; r++) {
                rv[r] = sRow[i * NTP + tn + r];
                PACK_DUP(nfnf[r], __float_as_uint(rv[r].y));
            }

            #pragma unroll
            for (int r = 0; r < NR; r++) {
                #pragma unroll
                for (int j = 0; j < OR; j++) {
                    float R = fmaf(rv[r].x, gj[j], 1.0f);  // a*g + (1-g)
                    float t = __log2f(R);                   // MUFU.LG2
                    unsigned long long tt;
                    PACK_DUP(tt, __float_as_uint(t));
                    FMA_F32X2(AB[r][j], tt, wj[j]);         // (A,B) += t*(wy,wz)
                    FMA_F32X2(AB[r][j], nfnf[r], pj[j]);    // (A,B) += nf*(Pa,Q)
                }
            }
        }
    }

    // ---- epilogue: out = exp(A) * cos(B) ----
    #pragma unroll
    for (int r = 0; r < NR; r++) {
        float4 v;
        float av[OR], bv[OR];
        #pragma unroll
        for (int j = 0; j < OR; j++) {
            av[j] = __uint_as_float((unsigned int)(AB[r][j] & 0xffffffffULL));
            bv[j] = __uint_as_float((unsigned int)(AB[r][j] >> 32));
        }
        v.x = expf(av[0]) * cosf(bv[0]);
        v.y = expf(av[1]) * cosf(bv[1]);
        v.z = expf(av[2]) * cosf(bv[2]);
        v.w = expf(av[3]) * cosf(bv[3]);
        *(float4*)&out[(n0 + tn + r) * DIM + o0 + to] = v;
    }
}

extern "C" void kernel_launch(void* const* d_in, const int* in_sizes, int n_in,
                              void* d_out, int out_size) {
    const float* x  = (const float*)d_in[0];
    const float* Wr = (const float*)d_in[1];
    const float* Wi = (const float*)d_in[2];
    const float* G  = (const float*)d_in[3];
    float* out = (float*)d_out;
    (void)in_sizes; (void)n_in; (void)out_size;

    NPU_prep_kernel<<<(DIM * DIM + 255) / 256, 256>>>(Wr, Wi, G);

    cudaFuncSetAttribute(NPU_main_kernel,
                         cudaFuncAttributeMaxDynamicSharedMemorySize, SMEM_TOTAL);
    dim3 grid(N_ROWS / NT, DIM / OT);
    NPU_main_kernel<<<grid, THREADS, SMEM_TOTAL>>>(x, out);
}